// round 13
// baseline (speedup 1.0000x reference)
#include <cuda_runtime.h>
#include <cuda_fp16.h>
#include <cstdint>
#include <mma.h>

using namespace nvcuda;

#define FEAT 128
#define NPAD 50176
#define LDH 136       // half stride (multiple of 8, LDSM conflict-free)
#define TILE_M 64
#define NTHR 512

// padded scratch buffers (gather never reads beyond row n)
__device__ __half g_vWn_h[NPAD * FEAT];   // v @ Wvn in fp16
__device__ float  g_Zc[NPAD * FEAT];      // v @ Wvc in fp32
// prepped neighbor data, transposed for coalescing
__device__ uint4 g_pidx[10 * NPAD];
__device__ uint4 g_pe2[10 * NPAD];

// ---------------------------------------------------------------------------
// Kernel 1: fused HMMA GEMM (2 sweeps sharing A fragments) + prep CTAs.
//   blockIdx.x <  nblk : 64x128 GEMM tile -> g_Zc (fp32), g_vWn_h (fp16)
//                        512 thr, 16 warps, warp tile 16x32 (high occupancy)
//   blockIdx.x >= nblk : neighbor prep (one thread per row, coalesced output)
// ---------------------------------------------------------------------------
__global__ __launch_bounds__(NTHR, 2) void fused_gemm_prep_kernel(
    const float* __restrict__ A,
    const float* __restrict__ Wvc,
    const float* __restrict__ Wvn,
    const int* __restrict__ nh_idx,
    const int* __restrict__ int_idx,
    const float* __restrict__ nh_e,
    const float* __restrict__ int_e,
    int n, int nblk)
{
    int tid = threadIdx.x;

    if ((int)blockIdx.x >= nblk) {
        // ------------------------- prep path ------------------------------
        int row = (blockIdx.x - nblk) * NTHR + tid;
        if (row >= n) return;

        int   idxs[40];
        float es[40];
        #pragma unroll
        for (int q = 0; q < 5; q++) {
            int4   a = __ldg(reinterpret_cast<const int4*>(nh_idx + row * 20) + q);
            float4 e = __ldg(reinterpret_cast<const float4*>(nh_e + row * 20) + q);
            idxs[4*q+0] = a.x; idxs[4*q+1] = a.y; idxs[4*q+2] = a.z; idxs[4*q+3] = a.w;
            es[4*q+0] = e.x; es[4*q+1] = e.y; es[4*q+2] = e.z; es[4*q+3] = e.w;
        }
        #pragma unroll
        for (int q = 0; q < 5; q++) {
            int4   a = __ldg(reinterpret_cast<const int4*>(int_idx + row * 20) + q);
            float4 e = __ldg(reinterpret_cast<const float4*>(int_e + row * 20) + q);
            idxs[20+4*q+0] = a.x; idxs[20+4*q+1] = a.y; idxs[20+4*q+2] = a.z; idxs[20+4*q+3] = a.w;
            es[20+4*q+0] = e.x; es[20+4*q+1] = e.y; es[20+4*q+2] = e.z; es[20+4*q+3] = e.w;
        }

        int cnt = 0;
        #pragma unroll
        for (int j = 0; j < 40; j++)
            cnt += (idxs[j] >= 0) ? 1 : 0;
        float inv = 1.0f / (float)cnt;

        #pragma unroll
        for (int q = 0; q < 10; q++) {
            uint32_t oi[4], oe[4];
            #pragma unroll
            for (int t = 0; t < 4; t++) {
                int j = 4 * q + t;
                bool v = idxs[j] >= 0;
                oi[t] = (uint32_t)(v ? idxs[j] : 0);
                __half2 h = __float2half2_rn(v ? es[j] * inv : 0.0f);
                oe[t] = *reinterpret_cast<uint32_t*>(&h);
            }
            g_pidx[q * NPAD + row] = make_uint4(oi[0], oi[1], oi[2], oi[3]);
            g_pe2[q * NPAD + row]  = make_uint4(oe[0], oe[1], oe[2], oe[3]);
        }
        return;
    }

    // --------------------------- GEMM path --------------------------------
    extern __shared__ __half sh[];
    __half* a1 = sh;                        // [TILE_M][LDH]
    __half* wc = sh + TILE_M * LDH;         // [128][LDH]
    __half* wn = sh + (TILE_M + 128) * LDH; // [128][LDH]

    int blockRow = blockIdx.x * TILE_M;

    #pragma unroll
    for (int i = tid; i < TILE_M * 32; i += NTHR) {
        int row = i >> 5, q = i & 31;
        int grow = blockRow + row;
        float4 v = make_float4(0.f, 0.f, 0.f, 0.f);
        if (grow < n) v = __ldg(reinterpret_cast<const float4*>(A) + grow * 32 + q);
        __half2* dst = reinterpret_cast<__half2*>(&a1[row * LDH + q * 4]);
        dst[0] = __floats2half2_rn(v.x, v.y);
        dst[1] = __floats2half2_rn(v.z, v.w);
    }
    #pragma unroll
    for (int i = tid; i < 128 * 32; i += NTHR) {
        int row = i >> 5, q = i & 31;
        float4 v = __ldg(reinterpret_cast<const float4*>(Wvc) + row * 32 + q);
        __half2* dst = reinterpret_cast<__half2*>(&wc[row * LDH + q * 4]);
        dst[0] = __floats2half2_rn(v.x, v.y);
        dst[1] = __floats2half2_rn(v.z, v.w);
    }
    #pragma unroll
    for (int i = tid; i < 128 * 32; i += NTHR) {
        int row = i >> 5, q = i & 31;
        float4 v = __ldg(reinterpret_cast<const float4*>(Wvn) + row * 32 + q);
        __half2* dst = reinterpret_cast<__half2*>(&wn[row * LDH + q * 4]);
        dst[0] = __floats2half2_rn(v.x, v.y);
        dst[1] = __floats2half2_rn(v.z, v.w);
    }
    __syncthreads();

    int w = tid >> 5;           // 0..15
    int m0 = (w & 3) * 16;      // 4 row groups of 16
    int n0 = (w >> 2) * 32;     // 4 col groups of 32

    wmma::fragment<wmma::accumulator, 16, 16, 16, float> accC[2], accN[2];
    #pragma unroll
    for (int j = 0; j < 2; j++) {
        wmma::fill_fragment(accC[j], 0.0f);
        wmma::fill_fragment(accN[j], 0.0f);
    }

    #pragma unroll
    for (int k = 0; k < 128; k += 16) {
        wmma::fragment<wmma::matrix_a, 16, 16, 16, __half, wmma::row_major> fa;
        wmma::load_matrix_sync(fa, &a1[m0 * LDH + k], LDH);
        #pragma unroll
        for (int j = 0; j < 2; j++) {
            wmma::fragment<wmma::matrix_b, 16, 16, 16, __half, wmma::row_major> fbC, fbN;
            wmma::load_matrix_sync(fbC, &wc[k * LDH + n0 + 16 * j], LDH);
            wmma::mma_sync(accC[j], fa, fbC, accC[j]);
            wmma::load_matrix_sync(fbN, &wn[k * LDH + n0 + 16 * j], LDH);
            wmma::mma_sync(accN[j], fa, fbN, accN[j]);
        }
    }

    #pragma unroll
    for (int j = 0; j < 2; j++)
        wmma::store_matrix_sync(
            g_Zc + (size_t)(blockRow + m0) * FEAT + n0 + 16 * j,
            accC[j], FEAT, wmma::mem_row_major);
    #pragma unroll
    for (int j = 0; j < 2; j++) {
        wmma::fragment<wmma::accumulator, 16, 16, 16, __half> ch;
        #pragma unroll
        for (int t = 0; t < ch.num_elements; t++)
            ch.x[t] = __float2half(accN[j].x[t]);
        wmma::store_matrix_sync(
            g_vWn_h + (size_t)(blockRow + m0) * FEAT + n0 + 16 * j,
            ch, FEAT, wmma::mem_row_major);
    }
}

// ---------------------------------------------------------------------------
// Kernel 2: gather — two rows per warp, LDG.128 gathers, HFMA2 accumulate.
// (At the L2-bandwidth floor: 2M row-gathers x 256B = 512MB / ~6300 B/cyc.)
// ---------------------------------------------------------------------------
__global__ __launch_bounds__(256, 5) void gather_kernel(
    float* __restrict__ out,
    const float* __restrict__ bv,
    int n)
{
    int warp = (blockIdx.x * blockDim.x + threadIdx.x) >> 5;
    int lane = threadIdx.x & 31;
    int half = lane >> 4;
    int sub  = lane & 15;
    int row  = warp * 2 + half;
    if (row >= n) return;

    const uint4* vW16 = reinterpret_cast<const uint4*>(g_vWn_h);

    __half2 accA[4], accB[4];
    #pragma unroll
    for (int c = 0; c < 4; c++) {
        accA[c] = __float2half2_rn(0.f);
        accB[c] = __float2half2_rn(0.f);
    }

    #pragma unroll
    for (int q = 0; q < 10; q++) {
        uint4 a = __ldg(&g_pidx[q * NPAD + row]);
        uint4 e = __ldg(&g_pe2[q * NPAD + row]);
        uint4 v0 = __ldg(vW16 + (size_t)a.x * 16 + sub);
        uint4 v1 = __ldg(vW16 + (size_t)a.y * 16 + sub);
        uint4 v2 = __ldg(vW16 + (size_t)a.z * 16 + sub);
        uint4 v3 = __ldg(vW16 + (size_t)a.w * 16 + sub);
        __half2 e0 = *reinterpret_cast<__half2*>(&e.x);
        __half2 e1 = *reinterpret_cast<__half2*>(&e.y);
        __half2 e2 = *reinterpret_cast<__half2*>(&e.z);
        __half2 e3 = *reinterpret_cast<__half2*>(&e.w);
        const uint32_t* p0 = &v0.x;
        const uint32_t* p1 = &v1.x;
        const uint32_t* p2 = &v2.x;
        const uint32_t* p3 = &v3.x;
        #pragma unroll
        for (int c = 0; c < 4; c++) {
            accA[c] = __hfma2(*reinterpret_cast<const __half2*>(p0 + c), e0, accA[c]);
            accB[c] = __hfma2(*reinterpret_cast<const __half2*>(p1 + c), e1, accB[c]);
            accA[c] = __hfma2(*reinterpret_cast<const __half2*>(p2 + c), e2, accA[c]);
            accB[c] = __hfma2(*reinterpret_cast<const __half2*>(p3 + c), e3, accB[c]);
        }
    }

    float2 f[4];
    #pragma unroll
    for (int c = 0; c < 4; c++)
        f[c] = __half22float2(__hadd2(accA[c], accB[c]));

    const float4* zc4 = reinterpret_cast<const float4*>(g_Zc) + (size_t)row * 32 + sub * 2;
    const float4* bv4 = reinterpret_cast<const float4*>(bv) + sub * 2;
    float4 zc0 = zc4[0], zc1 = zc4[1];
    float4 b0 = __ldg(bv4), b1 = __ldg(bv4 + 1);
    float4 z0, z1;
    z0.x = fmaxf(zc0.x + f[0].x + b0.x, 0.f);
    z0.y = fmaxf(zc0.y + f[0].y + b0.y, 0.f);
    z0.z = fmaxf(zc0.z + f[1].x + b0.z, 0.f);
    z0.w = fmaxf(zc0.w + f[1].y + b0.w, 0.f);
    z1.x = fmaxf(zc1.x + f[2].x + b1.x, 0.f);
    z1.y = fmaxf(zc1.y + f[2].y + b1.y, 0.f);
    z1.z = fmaxf(zc1.z + f[3].x + b1.z, 0.f);
    z1.w = fmaxf(zc1.w + f[3].y + b1.w, 0.f);
    float4* o4 = reinterpret_cast<float4*>(out) + (size_t)row * 32 + sub * 2;
    o4[0] = z0;
    o4[1] = z1;
}

// ---------------------------------------------------------------------------
extern "C" void kernel_launch(void* const* d_in, const int* in_sizes, int n_in,
                              void* d_out, int out_size) {
    const float* vertices    = (const float*)d_in[0];
    const int*   nh_indices  = (const int*)  d_in[1];
    const int*   int_indices = (const int*)  d_in[2];
    const float* nh_edges    = (const float*)d_in[3];
    const float* int_edges   = (const float*)d_in[4];
    const float* Wvc         = (const float*)d_in[5];
    const float* Wvn         = (const float*)d_in[6];
    const float* bv          = (const float*)d_in[7];
    float* out = (float*)d_out;

    int n = in_sizes[0] / FEAT;             // 50000
    int nblk = (n + TILE_M - 1) / TILE_M;   // 782
    int pblk = (n + NTHR - 1) / NTHR;       // 98

    static const size_t gemm_smem = (size_t)(TILE_M + 256) * LDH * sizeof(__half); // 87040
    cudaFuncSetAttribute(fused_gemm_prep_kernel,
                         cudaFuncAttributeMaxDynamicSharedMemorySize, (int)gemm_smem);

    fused_gemm_prep_kernel<<<nblk + pblk, NTHR, gemm_smem>>>(
        vertices, Wvc, Wvn, nh_indices, int_indices, nh_edges, int_edges, n, nblk);

    int nwarp = (n + 1) / 2;
    int g2 = (nwarp + 7) / 8;
    gather_kernel<<<g2, 256>>>(out, bv, n);
}

// round 14
// speedup vs baseline: 1.0664x; 1.0664x over previous
#include <cuda_runtime.h>
#include <cuda_fp16.h>
#include <cstdint>
#include <mma.h>

using namespace nvcuda;

#define FEAT 128
#define NPAD 50176
#define LDH 136       // A half-stride (multiple of 8)
#define LDN 72        // W half-stride (64 + 8 pad)
#define TILE_M 64

// padded scratch buffers (gather never reads beyond row n)
__device__ __half g_vWn_h[NPAD * FEAT];   // v @ Wvn in fp16
__device__ float  g_Zc[NPAD * FEAT];      // v @ Wvc in fp32
// prepped neighbor data, transposed for coalescing
__device__ uint4 g_pidx[10 * NPAD];
__device__ uint4 g_pe2[10 * NPAD];

// ---------------------------------------------------------------------------
// Kernel 1: fused HMMA GEMM (N-split for occupancy) + prep CTAs.
//   blockIdx.x < 2*nblkM : 64x64 GEMM tile (rowBlk = bx>>1, colHalf = bx&1)
//     smem = A(17.4KB) + 2 x W-half(18.4KB) = 54.2KB -> 3-4 CTAs/SM.
//     8 warps (4m x 2n), warp tile 16x32, accC[2]+accN[2].
//   blockIdx.x >= 2*nblkM : neighbor prep (one thread per row).
// ---------------------------------------------------------------------------
__global__ __launch_bounds__(256, 3) void fused_gemm_prep_kernel(
    const float* __restrict__ A,
    const float* __restrict__ Wvc,
    const float* __restrict__ Wvn,
    const int* __restrict__ nh_idx,
    const int* __restrict__ int_idx,
    const float* __restrict__ nh_e,
    const float* __restrict__ int_e,
    int n, int ngemm)
{
    int tid = threadIdx.x;

    if ((int)blockIdx.x >= ngemm) {
        // ------------------------- prep path ------------------------------
        int row = (blockIdx.x - ngemm) * 256 + tid;
        if (row >= n) return;

        int   idxs[40];
        float es[40];
        #pragma unroll
        for (int q = 0; q < 5; q++) {
            int4   a = __ldg(reinterpret_cast<const int4*>(nh_idx + row * 20) + q);
            float4 e = __ldg(reinterpret_cast<const float4*>(nh_e + row * 20) + q);
            idxs[4*q+0] = a.x; idxs[4*q+1] = a.y; idxs[4*q+2] = a.z; idxs[4*q+3] = a.w;
            es[4*q+0] = e.x; es[4*q+1] = e.y; es[4*q+2] = e.z; es[4*q+3] = e.w;
        }
        #pragma unroll
        for (int q = 0; q < 5; q++) {
            int4   a = __ldg(reinterpret_cast<const int4*>(int_idx + row * 20) + q);
            float4 e = __ldg(reinterpret_cast<const float4*>(int_e + row * 20) + q);
            idxs[20+4*q+0] = a.x; idxs[20+4*q+1] = a.y; idxs[20+4*q+2] = a.z; idxs[20+4*q+3] = a.w;
            es[20+4*q+0] = e.x; es[20+4*q+1] = e.y; es[20+4*q+2] = e.z; es[20+4*q+3] = e.w;
        }

        int cnt = 0;
        #pragma unroll
        for (int j = 0; j < 40; j++)
            cnt += (idxs[j] >= 0) ? 1 : 0;
        float inv = 1.0f / (float)cnt;

        #pragma unroll
        for (int q = 0; q < 10; q++) {
            uint32_t oi[4], oe[4];
            #pragma unroll
            for (int t = 0; t < 4; t++) {
                int j = 4 * q + t;
                bool v = idxs[j] >= 0;
                oi[t] = (uint32_t)(v ? idxs[j] : 0);
                __half2 h = __float2half2_rn(v ? es[j] * inv : 0.0f);
                oe[t] = *reinterpret_cast<uint32_t*>(&h);
            }
            g_pidx[q * NPAD + row] = make_uint4(oi[0], oi[1], oi[2], oi[3]);
            g_pe2[q * NPAD + row]  = make_uint4(oe[0], oe[1], oe[2], oe[3]);
        }
        return;
    }

    // --------------------------- GEMM path --------------------------------
    extern __shared__ __half sh[];
    __half* a1 = sh;                        // [TILE_M][LDH]
    __half* wc = sh + TILE_M * LDH;         // [128][LDN]
    __half* wn = sh + TILE_M * LDH + 128 * LDN; // [128][LDN]

    int rowBlk  = blockIdx.x >> 1;
    int colBase = (blockIdx.x & 1) * 64;
    int blockRow = rowBlk * TILE_M;

    // ---- load A tile (guarded) ----
    #pragma unroll
    for (int i = tid; i < TILE_M * 32; i += 256) {
        int row = i >> 5, q = i & 31;
        int grow = blockRow + row;
        float4 v = make_float4(0.f, 0.f, 0.f, 0.f);
        if (grow < n) v = __ldg(reinterpret_cast<const float4*>(A) + grow * 32 + q);
        __half2* dst = reinterpret_cast<__half2*>(&a1[row * LDH + q * 4]);
        dst[0] = __floats2half2_rn(v.x, v.y);
        dst[1] = __floats2half2_rn(v.z, v.w);
    }
    // ---- load W halves (64 cols each, unguarded) ----
    #pragma unroll
    for (int i = tid; i < 128 * 16; i += 256) {
        int row = i >> 4, q = i & 15;
        float4 v = __ldg(reinterpret_cast<const float4*>(Wvc) + row * 32 + (colBase >> 2) + q);
        __half2* dst = reinterpret_cast<__half2*>(&wc[row * LDN + q * 4]);
        dst[0] = __floats2half2_rn(v.x, v.y);
        dst[1] = __floats2half2_rn(v.z, v.w);
    }
    #pragma unroll
    for (int i = tid; i < 128 * 16; i += 256) {
        int row = i >> 4, q = i & 15;
        float4 v = __ldg(reinterpret_cast<const float4*>(Wvn) + row * 32 + (colBase >> 2) + q);
        __half2* dst = reinterpret_cast<__half2*>(&wn[row * LDN + q * 4]);
        dst[0] = __floats2half2_rn(v.x, v.y);
        dst[1] = __floats2half2_rn(v.z, v.w);
    }
    __syncthreads();

    int w = tid >> 5;           // 0..7
    int m0 = (w & 3) * 16;      // 4 row groups of 16
    int n0 = (w >> 2) * 32;     // 2 col groups of 32

    wmma::fragment<wmma::accumulator, 16, 16, 16, float> accC[2], accN[2];
    #pragma unroll
    for (int j = 0; j < 2; j++) {
        wmma::fill_fragment(accC[j], 0.0f);
        wmma::fill_fragment(accN[j], 0.0f);
    }

    #pragma unroll
    for (int k = 0; k < 128; k += 16) {
        wmma::fragment<wmma::matrix_a, 16, 16, 16, __half, wmma::row_major> fa;
        wmma::load_matrix_sync(fa, &a1[m0 * LDH + k], LDH);
        #pragma unroll
        for (int j = 0; j < 2; j++) {
            wmma::fragment<wmma::matrix_b, 16, 16, 16, __half, wmma::row_major> fbC, fbN;
            wmma::load_matrix_sync(fbC, &wc[k * LDN + n0 + 16 * j], LDN);
            wmma::mma_sync(accC[j], fa, fbC, accC[j]);
            wmma::load_matrix_sync(fbN, &wn[k * LDN + n0 + 16 * j], LDN);
            wmma::mma_sync(accN[j], fa, fbN, accN[j]);
        }
    }

    #pragma unroll
    for (int j = 0; j < 2; j++)
        wmma::store_matrix_sync(
            g_Zc + (size_t)(blockRow + m0) * FEAT + colBase + n0 + 16 * j,
            accC[j], FEAT, wmma::mem_row_major);
    #pragma unroll
    for (int j = 0; j < 2; j++) {
        wmma::fragment<wmma::accumulator, 16, 16, 16, __half> ch;
        #pragma unroll
        for (int t = 0; t < ch.num_elements; t++)
            ch.x[t] = __float2half(accN[j].x[t]);
        wmma::store_matrix_sync(
            g_vWn_h + (size_t)(blockRow + m0) * FEAT + colBase + n0 + 16 * j,
            ch, FEAT, wmma::mem_row_major);
    }
}

// ---------------------------------------------------------------------------
// Kernel 2: gather — two rows per warp, LDG.128 gathers, HFMA2 accumulate.
// (At the L2-bandwidth floor: 2M row-gathers x 256B = 512MB / ~6300 B/cyc.)
// ---------------------------------------------------------------------------
__global__ __launch_bounds__(256, 5) void gather_kernel(
    float* __restrict__ out,
    const float* __restrict__ bv,
    int n)
{
    int warp = (blockIdx.x * blockDim.x + threadIdx.x) >> 5;
    int lane = threadIdx.x & 31;
    int half = lane >> 4;
    int sub  = lane & 15;
    int row  = warp * 2 + half;
    if (row >= n) return;

    const uint4* vW16 = reinterpret_cast<const uint4*>(g_vWn_h);

    __half2 accA[4], accB[4];
    #pragma unroll
    for (int c = 0; c < 4; c++) {
        accA[c] = __float2half2_rn(0.f);
        accB[c] = __float2half2_rn(0.f);
    }

    #pragma unroll
    for (int q = 0; q < 10; q++) {
        uint4 a = __ldg(&g_pidx[q * NPAD + row]);
        uint4 e = __ldg(&g_pe2[q * NPAD + row]);
        uint4 v0 = __ldg(vW16 + (size_t)a.x * 16 + sub);
        uint4 v1 = __ldg(vW16 + (size_t)a.y * 16 + sub);
        uint4 v2 = __ldg(vW16 + (size_t)a.z * 16 + sub);
        uint4 v3 = __ldg(vW16 + (size_t)a.w * 16 + sub);
        __half2 e0 = *reinterpret_cast<__half2*>(&e.x);
        __half2 e1 = *reinterpret_cast<__half2*>(&e.y);
        __half2 e2 = *reinterpret_cast<__half2*>(&e.z);
        __half2 e3 = *reinterpret_cast<__half2*>(&e.w);
        const uint32_t* p0 = &v0.x;
        const uint32_t* p1 = &v1.x;
        const uint32_t* p2 = &v2.x;
        const uint32_t* p3 = &v3.x;
        #pragma unroll
        for (int c = 0; c < 4; c++) {
            accA[c] = __hfma2(*reinterpret_cast<const __half2*>(p0 + c), e0, accA[c]);
            accB[c] = __hfma2(*reinterpret_cast<const __half2*>(p1 + c), e1, accB[c]);
            accA[c] = __hfma2(*reinterpret_cast<const __half2*>(p2 + c), e2, accA[c]);
            accB[c] = __hfma2(*reinterpret_cast<const __half2*>(p3 + c), e3, accB[c]);
        }
    }

    float2 f[4];
    #pragma unroll
    for (int c = 0; c < 4; c++)
        f[c] = __half22float2(__hadd2(accA[c], accB[c]));

    const float4* zc4 = reinterpret_cast<const float4*>(g_Zc) + (size_t)row * 32 + sub * 2;
    const float4* bv4 = reinterpret_cast<const float4*>(bv) + sub * 2;
    float4 zc0 = zc4[0], zc1 = zc4[1];
    float4 b0 = __ldg(bv4), b1 = __ldg(bv4 + 1);
    float4 z0, z1;
    z0.x = fmaxf(zc0.x + f[0].x + b0.x, 0.f);
    z0.y = fmaxf(zc0.y + f[0].y + b0.y, 0.f);
    z0.z = fmaxf(zc0.z + f[1].x + b0.z, 0.f);
    z0.w = fmaxf(zc0.w + f[1].y + b0.w, 0.f);
    z1.x = fmaxf(zc1.x + f[2].x + b1.x, 0.f);
    z1.y = fmaxf(zc1.y + f[2].y + b1.y, 0.f);
    z1.z = fmaxf(zc1.z + f[3].x + b1.z, 0.f);
    z1.w = fmaxf(zc1.w + f[3].y + b1.w, 0.f);
    float4* o4 = reinterpret_cast<float4*>(out) + (size_t)row * 32 + sub * 2;
    o4[0] = z0;
    o4[1] = z1;
}

// ---------------------------------------------------------------------------
extern "C" void kernel_launch(void* const* d_in, const int* in_sizes, int n_in,
                              void* d_out, int out_size) {
    const float* vertices    = (const float*)d_in[0];
    const int*   nh_indices  = (const int*)  d_in[1];
    const int*   int_indices = (const int*)  d_in[2];
    const float* nh_edges    = (const float*)d_in[3];
    const float* int_edges   = (const float*)d_in[4];
    const float* Wvc         = (const float*)d_in[5];
    const float* Wvn         = (const float*)d_in[6];
    const float* bv          = (const float*)d_in[7];
    float* out = (float*)d_out;

    int n = in_sizes[0] / FEAT;                 // 50000
    int ngemm = 2 * ((n + TILE_M - 1) / TILE_M);  // 1564
    int pblk = (n + 255) / 256;                 // 196

    static const size_t gemm_smem =
        (size_t)(TILE_M * LDH + 2 * 128 * LDN) * sizeof(__half);  // 54272
    cudaFuncSetAttribute(fused_gemm_prep_kernel,
                         cudaFuncAttributeMaxDynamicSharedMemorySize, (int)gemm_smem);

    fused_gemm_prep_kernel<<<ngemm + pblk, 256, gemm_smem>>>(
        vertices, Wvc, Wvn, nh_indices, int_indices, nh_edges, int_edges, n, ngemm);

    int nwarp = (n + 1) / 2;
    int g2 = (nwarp + 7) / 8;
    gather_kernel<<<g2, 256>>>(out, bv, n);
}

// round 15
// speedup vs baseline: 1.1764x; 1.1032x over previous
#include <cuda_runtime.h>
#include <cuda_fp16.h>
#include <cstdint>
#include <mma.h>

using namespace nvcuda;

#define FEAT 128
#define NPAD 50176
#define LDH 136       // half stride (multiple of 8, LDSM conflict-free)
#define TILE_M 64
#define NGEMM 296     // persistent GEMM CTAs (148 SMs x 2)

// padded scratch buffers (gather never reads beyond row n)
__device__ __half g_vWn_h[NPAD * FEAT];   // v @ Wvn in fp16
__device__ __half g_Zc_h[NPAD * FEAT];    // v @ Wvc in fp16
// prepped neighbor data, transposed for coalescing
__device__ uint4 g_pidx[10 * NPAD];
__device__ uint4 g_pe2[10 * NPAD];

// ---------------------------------------------------------------------------
// Kernel 1: persistent fused HMMA GEMM + prep CTAs.
//   blockIdx.x < NGEMM : persistent GEMM worker. Loads/converts both W tiles
//     ONCE, then grid-strides over 64x128 row tiles: A-load + 2-sweep MMA +
//     fp16 epilogues. 8 warps, warp tile 16x64 per output.
//   blockIdx.x >= NGEMM : neighbor prep (one thread per row).
// ---------------------------------------------------------------------------
__global__ __launch_bounds__(256, 2) void fused_gemm_prep_kernel(
    const float* __restrict__ A,
    const float* __restrict__ Wvc,
    const float* __restrict__ Wvn,
    const int* __restrict__ nh_idx,
    const int* __restrict__ int_idx,
    const float* __restrict__ nh_e,
    const float* __restrict__ int_e,
    int n, int ntiles)
{
    int tid = threadIdx.x;

    if ((int)blockIdx.x >= NGEMM) {
        // ------------------------- prep path ------------------------------
        int row = (blockIdx.x - NGEMM) * 256 + tid;
        if (row >= n) return;

        int   idxs[40];
        float es[40];
        #pragma unroll
        for (int q = 0; q < 5; q++) {
            int4   a = __ldg(reinterpret_cast<const int4*>(nh_idx + row * 20) + q);
            float4 e = __ldg(reinterpret_cast<const float4*>(nh_e + row * 20) + q);
            idxs[4*q+0] = a.x; idxs[4*q+1] = a.y; idxs[4*q+2] = a.z; idxs[4*q+3] = a.w;
            es[4*q+0] = e.x; es[4*q+1] = e.y; es[4*q+2] = e.z; es[4*q+3] = e.w;
        }
        #pragma unroll
        for (int q = 0; q < 5; q++) {
            int4   a = __ldg(reinterpret_cast<const int4*>(int_idx + row * 20) + q);
            float4 e = __ldg(reinterpret_cast<const float4*>(int_e + row * 20) + q);
            idxs[20+4*q+0] = a.x; idxs[20+4*q+1] = a.y; idxs[20+4*q+2] = a.z; idxs[20+4*q+3] = a.w;
            es[20+4*q+0] = e.x; es[20+4*q+1] = e.y; es[20+4*q+2] = e.z; es[20+4*q+3] = e.w;
        }

        int cnt = 0;
        #pragma unroll
        for (int j = 0; j < 40; j++)
            cnt += (idxs[j] >= 0) ? 1 : 0;
        float inv = 1.0f / (float)cnt;

        #pragma unroll
        for (int q = 0; q < 10; q++) {
            uint32_t oi[4], oe[4];
            #pragma unroll
            for (int t = 0; t < 4; t++) {
                int j = 4 * q + t;
                bool v = idxs[j] >= 0;
                oi[t] = (uint32_t)(v ? idxs[j] : 0);
                __half2 h = __float2half2_rn(v ? es[j] * inv : 0.0f);
                oe[t] = *reinterpret_cast<uint32_t*>(&h);
            }
            g_pidx[q * NPAD + row] = make_uint4(oi[0], oi[1], oi[2], oi[3]);
            g_pe2[q * NPAD + row]  = make_uint4(oe[0], oe[1], oe[2], oe[3]);
        }
        return;
    }

    // --------------------------- GEMM path --------------------------------
    extern __shared__ __half sh[];
    __half* a1 = sh;                        // [TILE_M][LDH]
    __half* wc = sh + TILE_M * LDH;         // [128][LDH]
    __half* wn = sh + (TILE_M + 128) * LDH; // [128][LDH]

    // ---- load + convert both W tiles ONCE ----
    #pragma unroll
    for (int i = tid; i < 128 * 32; i += 256) {
        int row = i >> 5, q = i & 31;
        float4 v = __ldg(reinterpret_cast<const float4*>(Wvc) + row * 32 + q);
        __half2* dst = reinterpret_cast<__half2*>(&wc[row * LDH + q * 4]);
        dst[0] = __floats2half2_rn(v.x, v.y);
        dst[1] = __floats2half2_rn(v.z, v.w);
    }
    #pragma unroll
    for (int i = tid; i < 128 * 32; i += 256) {
        int row = i >> 5, q = i & 31;
        float4 v = __ldg(reinterpret_cast<const float4*>(Wvn) + row * 32 + q);
        __half2* dst = reinterpret_cast<__half2*>(&wn[row * LDH + q * 4]);
        dst[0] = __floats2half2_rn(v.x, v.y);
        dst[1] = __floats2half2_rn(v.z, v.w);
    }

    int w = tid >> 5;
    int m0 = (w & 3) * 16;      // 4 row groups of 16
    int n0 = (w >> 2) * 64;     // 2 col groups of 64

    for (int t = blockIdx.x; t < ntiles; t += NGEMM) {
        int blockRow = t * TILE_M;

        // ---- load A tile (guarded) ----
        #pragma unroll
        for (int i = tid; i < TILE_M * 32; i += 256) {
            int row = i >> 5, q = i & 31;
            int grow = blockRow + row;
            float4 v = make_float4(0.f, 0.f, 0.f, 0.f);
            if (grow < n) v = __ldg(reinterpret_cast<const float4*>(A) + grow * 32 + q);
            __half2* dst = reinterpret_cast<__half2*>(&a1[row * LDH + q * 4]);
            dst[0] = __floats2half2_rn(v.x, v.y);
            dst[1] = __floats2half2_rn(v.z, v.w);
        }
        __syncthreads();

        wmma::fragment<wmma::accumulator, 16, 16, 16, float> accC[4], accN[4];
        #pragma unroll
        for (int j = 0; j < 4; j++) {
            wmma::fill_fragment(accC[j], 0.0f);
            wmma::fill_fragment(accN[j], 0.0f);
        }

        #pragma unroll
        for (int k = 0; k < 128; k += 16) {
            wmma::fragment<wmma::matrix_a, 16, 16, 16, __half, wmma::row_major> fa;
            wmma::load_matrix_sync(fa, &a1[m0 * LDH + k], LDH);
            #pragma unroll
            for (int j = 0; j < 4; j++) {
                wmma::fragment<wmma::matrix_b, 16, 16, 16, __half, wmma::row_major> fbC, fbN;
                wmma::load_matrix_sync(fbC, &wc[k * LDH + n0 + 16 * j], LDH);
                wmma::mma_sync(accC[j], fa, fbC, accC[j]);
                wmma::load_matrix_sync(fbN, &wn[k * LDH + n0 + 16 * j], LDH);
                wmma::mma_sync(accN[j], fa, fbN, accN[j]);
            }
        }

        // ---- epilogues: both outputs fp16, padded buffers (no guards) ----
        #pragma unroll
        for (int j = 0; j < 4; j++) {
            wmma::fragment<wmma::accumulator, 16, 16, 16, __half> ch;
            #pragma unroll
            for (int u = 0; u < ch.num_elements; u++)
                ch.x[u] = __float2half(accC[j].x[u]);
            wmma::store_matrix_sync(
                g_Zc_h + (size_t)(blockRow + m0) * FEAT + n0 + 16 * j,
                ch, FEAT, wmma::mem_row_major);
        }
        #pragma unroll
        for (int j = 0; j < 4; j++) {
            wmma::fragment<wmma::accumulator, 16, 16, 16, __half> ch;
            #pragma unroll
            for (int u = 0; u < ch.num_elements; u++)
                ch.x[u] = __float2half(accN[j].x[u]);
            wmma::store_matrix_sync(
                g_vWn_h + (size_t)(blockRow + m0) * FEAT + n0 + 16 * j,
                ch, FEAT, wmma::mem_row_major);
        }
        __syncthreads();   // a1 reused next iteration
    }
}

// ---------------------------------------------------------------------------
// Kernel 2: gather — two rows per warp, LDG.128 gathers, HFMA2 accumulate.
// (At the L2-bandwidth floor: 2M row-gathers x 256B.)  Zc now read as fp16.
// ---------------------------------------------------------------------------
__global__ __launch_bounds__(256, 5) void gather_kernel(
    float* __restrict__ out,
    const float* __restrict__ bv,
    int n)
{
    int warp = (blockIdx.x * blockDim.x + threadIdx.x) >> 5;
    int lane = threadIdx.x & 31;
    int half = lane >> 4;
    int sub  = lane & 15;
    int row  = warp * 2 + half;
    if (row >= n) return;

    const uint4* vW16 = reinterpret_cast<const uint4*>(g_vWn_h);

    __half2 accA[4], accB[4];
    #pragma unroll
    for (int c = 0; c < 4; c++) {
        accA[c] = __float2half2_rn(0.f);
        accB[c] = __float2half2_rn(0.f);
    }

    #pragma unroll
    for (int q = 0; q < 10; q++) {
        uint4 a = __ldg(&g_pidx[q * NPAD + row]);
        uint4 e = __ldg(&g_pe2[q * NPAD + row]);
        uint4 v0 = __ldg(vW16 + (size_t)a.x * 16 + sub);
        uint4 v1 = __ldg(vW16 + (size_t)a.y * 16 + sub);
        uint4 v2 = __ldg(vW16 + (size_t)a.z * 16 + sub);
        uint4 v3 = __ldg(vW16 + (size_t)a.w * 16 + sub);
        __half2 e0 = *reinterpret_cast<__half2*>(&e.x);
        __half2 e1 = *reinterpret_cast<__half2*>(&e.y);
        __half2 e2 = *reinterpret_cast<__half2*>(&e.z);
        __half2 e3 = *reinterpret_cast<__half2*>(&e.w);
        const uint32_t* p0 = &v0.x;
        const uint32_t* p1 = &v1.x;
        const uint32_t* p2 = &v2.x;
        const uint32_t* p3 = &v3.x;
        #pragma unroll
        for (int c = 0; c < 4; c++) {
            accA[c] = __hfma2(*reinterpret_cast<const __half2*>(p0 + c), e0, accA[c]);
            accB[c] = __hfma2(*reinterpret_cast<const __half2*>(p1 + c), e1, accB[c]);
            accA[c] = __hfma2(*reinterpret_cast<const __half2*>(p2 + c), e2, accA[c]);
            accB[c] = __hfma2(*reinterpret_cast<const __half2*>(p3 + c), e3, accB[c]);
        }
    }

    float2 f[4];
    #pragma unroll
    for (int c = 0; c < 4; c++)
        f[c] = __half22float2(__hadd2(accA[c], accB[c]));

    // Zc (fp16, 8 halves = 16B per sub-lane) + bias
    uint4 zcr = __ldg(reinterpret_cast<const uint4*>(g_Zc_h) + (size_t)row * 16 + sub);
    const __half2* zh = reinterpret_cast<const __half2*>(&zcr);
    float2 zc01 = __half22float2(zh[0]);
    float2 zc23 = __half22float2(zh[1]);
    float2 zc45 = __half22float2(zh[2]);
    float2 zc67 = __half22float2(zh[3]);

    const float4* bv4 = reinterpret_cast<const float4*>(bv) + sub * 2;
    float4 b0 = __ldg(bv4), b1 = __ldg(bv4 + 1);

    float4 z0, z1;
    z0.x = fmaxf(zc01.x + f[0].x + b0.x, 0.f);
    z0.y = fmaxf(zc01.y + f[0].y + b0.y, 0.f);
    z0.z = fmaxf(zc23.x + f[1].x + b0.z, 0.f);
    z0.w = fmaxf(zc23.y + f[1].y + b0.w, 0.f);
    z1.x = fmaxf(zc45.x + f[2].x + b1.x, 0.f);
    z1.y = fmaxf(zc45.y + f[2].y + b1.y, 0.f);
    z1.z = fmaxf(zc67.x + f[3].x + b1.z, 0.f);
    z1.w = fmaxf(zc67.y + f[3].y + b1.w, 0.f);
    float4* o4 = reinterpret_cast<float4*>(out) + (size_t)row * 32 + sub * 2;
    o4[0] = z0;
    o4[1] = z1;
}

// ---------------------------------------------------------------------------
extern "C" void kernel_launch(void* const* d_in, const int* in_sizes, int n_in,
                              void* d_out, int out_size) {
    const float* vertices    = (const float*)d_in[0];
    const int*   nh_indices  = (const int*)  d_in[1];
    const int*   int_indices = (const int*)  d_in[2];
    const float* nh_edges    = (const float*)d_in[3];
    const float* int_edges   = (const float*)d_in[4];
    const float* Wvc         = (const float*)d_in[5];
    const float* Wvn         = (const float*)d_in[6];
    const float* bv          = (const float*)d_in[7];
    float* out = (float*)d_out;

    int n = in_sizes[0] / FEAT;               // 50000
    int ntiles = (n + TILE_M - 1) / TILE_M;   // 782
    int pblk = (n + 255) / 256;               // 196

    static const size_t gemm_smem = (size_t)(TILE_M + 256) * LDH * sizeof(__half); // 87040
    cudaFuncSetAttribute(fused_gemm_prep_kernel,
                         cudaFuncAttributeMaxDynamicSharedMemorySize, (int)gemm_smem);

    fused_gemm_prep_kernel<<<NGEMM + pblk, 256, gemm_smem>>>(
        vertices, Wvc, Wvn, nh_indices, int_indices, nh_edges, int_edges, n, ntiles);

    int nwarp = (n + 1) / 2;
    int g2 = (nwarp + 7) / 8;
    gather_kernel<<<g2, 256>>>(out, bv, n);
}